// round 1
// baseline (speedup 1.0000x reference)
#include <cuda_runtime.h>

#define Dd 96
#define Hh 160
#define Ww 160
#define DHW (Dd*Hh*Ww)

// scratch: two composed-flow fields (3 channels each)
__device__ float g_bufA[3 * DHW];
__device__ float g_bufB[3 * DHW];

// coord(v,s) = v*s/(s-1) - 0.5  (normalize_grid + grid_sample denorm, fused)
#define SZC ((float)Dd / (float)(Dd - 1))
#define SYC ((float)Hh / (float)(Hh - 1))
#define SXC ((float)Ww / (float)(Ww - 1))

// Build 8 clamped corner offsets + zero-padded trilinear weights.
__device__ __forceinline__ void make_corners(float cz, float cy, float cx,
                                             int off[8], float w[8]) {
    float z0f = floorf(cz), y0f = floorf(cy), x0f = floorf(cx);
    float tz = cz - z0f, ty = cy - y0f, tx = cx - x0f;
    int z0 = (int)z0f, y0 = (int)y0f, x0 = (int)x0f;
    int z1 = z0 + 1,  y1 = y0 + 1,  x1 = x0 + 1;

    float wz0 = (z0 >= 0 && z0 < Dd) ? (1.f - tz) : 0.f;
    float wz1 = (z1 >= 0 && z1 < Dd) ? tz         : 0.f;
    float wy0 = (y0 >= 0 && y0 < Hh) ? (1.f - ty) : 0.f;
    float wy1 = (y1 >= 0 && y1 < Hh) ? ty         : 0.f;
    float wx0 = (x0 >= 0 && x0 < Ww) ? (1.f - tx) : 0.f;
    float wx1 = (x1 >= 0 && x1 < Ww) ? tx         : 0.f;

    int z0c = min(max(z0, 0), Dd - 1), z1c = min(max(z1, 0), Dd - 1);
    int y0c = min(max(y0, 0), Hh - 1), y1c = min(max(y1, 0), Hh - 1);
    int x0c = min(max(x0, 0), Ww - 1), x1c = min(max(x1, 0), Ww - 1);

    int b00 = (z0c * Hh + y0c) * Ww;
    int b01 = (z0c * Hh + y1c) * Ww;
    int b10 = (z1c * Hh + y0c) * Ww;
    int b11 = (z1c * Hh + y1c) * Ww;

    off[0] = b00 + x0c;  w[0] = wz0 * wy0 * wx0;
    off[1] = b00 + x1c;  w[1] = wz0 * wy0 * wx1;
    off[2] = b01 + x0c;  w[2] = wz0 * wy1 * wx0;
    off[3] = b01 + x1c;  w[3] = wz0 * wy1 * wx1;
    off[4] = b10 + x0c;  w[4] = wz1 * wy0 * wx0;
    off[5] = b10 + x1c;  w[5] = wz1 * wy0 * wx1;
    off[6] = b11 + x0c;  w[6] = wz1 * wy1 * wx0;
    off[7] = b11 + x1c;  w[7] = wz1 * wy1 * wx1;
}

// One compose step: out = trilerp(comp, base + dvf*rf) + dvf   (3 channels)
__global__ void __launch_bounds__(256)
warp_step(const float* __restrict__ comp, const float* __restrict__ dvf,
          float* __restrict__ out, const float* __restrict__ rfp) {
    int idx = blockIdx.x * blockDim.x + threadIdx.x;
    if (idx >= DHW) return;
    float rf = __ldg(rfp);

    int x = idx % Ww;
    int y = (idx / Ww) % Hh;
    int z = idx / (Ww * Hh);

    float fz = dvf[idx];
    float fy = dvf[idx + DHW];
    float fx = dvf[idx + 2 * DHW];

    float cz = fmaf(fz * rf, SZC, (float)z * SZC - 0.5f);
    float cy = fmaf(fy * rf, SYC, (float)y * SYC - 0.5f);
    float cx = fmaf(fx * rf, SXC, (float)x * SXC - 0.5f);

    int off[8]; float w[8];
    make_corners(cz, cy, cx, off, w);

    float add[3] = {fz, fy, fx};
    #pragma unroll
    for (int c = 0; c < 3; c++) {
        const float* ch = comp + c * DHW;
        float s = 0.f;
        #pragma unroll
        for (int k = 0; k < 8; k++) s = fmaf(w[k], __ldg(ch + off[k]), s);
        out[c * DHW + idx] = s + add[c];
    }
}

// Final step fused: composed3 = trilerp(comp, base+ff*rf) + ff  -> out_flow
//                   deform    = trilerp(src,  base+composed3*rf)
__global__ void __launch_bounds__(256)
warp_final(const float* __restrict__ comp, const float* __restrict__ ff,
           const float* __restrict__ src, float* __restrict__ out_deform,
           float* __restrict__ out_flow, const float* __restrict__ rfp) {
    int idx = blockIdx.x * blockDim.x + threadIdx.x;
    if (idx >= DHW) return;
    float rf = __ldg(rfp);

    int x = idx % Ww;
    int y = (idx / Ww) % Hh;
    int z = idx / (Ww * Hh);

    float fz = ff[idx];
    float fy = ff[idx + DHW];
    float fx = ff[idx + 2 * DHW];

    float cz = fmaf(fz * rf, SZC, (float)z * SZC - 0.5f);
    float cy = fmaf(fy * rf, SYC, (float)y * SYC - 0.5f);
    float cx = fmaf(fx * rf, SXC, (float)x * SXC - 0.5f);

    int off[8]; float w[8];
    make_corners(cz, cy, cx, off, w);

    float compo[3];
    float add[3] = {fz, fy, fx};
    #pragma unroll
    for (int c = 0; c < 3; c++) {
        const float* ch = comp + c * DHW;
        float s = 0.f;
        #pragma unroll
        for (int k = 0; k < 8; k++) s = fmaf(w[k], __ldg(ch + off[k]), s);
        compo[c] = s + add[c];
        out_flow[c * DHW + idx] = compo[c];
    }

    // second sample: src at base + composed3*rf
    float cz2 = fmaf(compo[0] * rf, SZC, (float)z * SZC - 0.5f);
    float cy2 = fmaf(compo[1] * rf, SYC, (float)y * SYC - 0.5f);
    float cx2 = fmaf(compo[2] * rf, SXC, (float)x * SXC - 0.5f);

    int off2[8]; float w2[8];
    make_corners(cz2, cy2, cx2, off2, w2);

    float s = 0.f;
    #pragma unroll
    for (int k = 0; k < 8; k++) s = fmaf(w2[k], __ldg(src + off2[k]), s);
    out_deform[idx] = s;
}

extern "C" void kernel_launch(void* const* d_in, const int* in_sizes, int n_in,
                              void* d_out, int out_size) {
    const float* src        = (const float*)d_in[0];   // [1,1,D,H,W]
    const float* flow_list  = (const float*)d_in[1];   // [3,1,3,D,H,W]
    const float* final_flow = (const float*)d_in[2];   // [1,3,D,H,W]
    const float* rfp        = (const float*)d_in[3];   // scalar

    float* out_deform = (float*)d_out;          // [D*H*W]
    float* out_flow   = (float*)d_out + DHW;    // [3*D*H*W]

    float *bufA, *bufB;
    cudaGetSymbolAddress((void**)&bufA, g_bufA);
    cudaGetSymbolAddress((void**)&bufB, g_bufB);

    const int threads = 256;
    const int blocks = (DHW + threads - 1) / threads;

    // iter 1: comp = flow_list[0], dvf = flow_list[1] -> bufA
    warp_step<<<blocks, threads>>>(flow_list, flow_list + 3 * DHW, bufA, rfp);
    // iter 2: comp = bufA, dvf = flow_list[2] -> bufB
    warp_step<<<blocks, threads>>>(bufA, flow_list + 6 * DHW, bufB, rfp);
    // iter 3 + final sample fused
    warp_final<<<blocks, threads>>>(bufB, final_flow, src, out_deform, out_flow, rfp);
}